// round 9
// baseline (speedup 1.0000x reference)
#include <cuda_runtime.h>

#define NNODES 3000
#define BATCH  16
#define FEAT   43
#define NREL   3
#define NBUCKET (NREL*NNODES)
#define ROWS   (BATCH*NNODES)     // 48000
#define GBN    8                  // nodes per block in RGCN kernel
#define OBSTR  129                // padded stride for obs staging (bank-conflict free)

// ---------------- scratch (static __device__, no allocation) ----------------
__device__ float d_x [BATCH*NNODES*FEAT];   // temporal features
__device__ float d_h1[BATCH*NNODES*FEAT];   // after RGCN layer 1
__device__ float d_h2[BATCH*NNODES*FEAT];   // after RGCN layer 2
__device__ int   dc_cnt[NBUCKET];
__device__ int   dc_off[NBUCKET+1];
__device__ int   dc_cur[NBUCKET];
__device__ float dc_inv[NBUCKET];
__device__ int   dc_src[96000];

// ---------------- CSR build ----------------
__global__ void k_zero() {
    int i = blockIdx.x*blockDim.x + threadIdx.x;
    if (i < NBUCKET) dc_cnt[i] = 0;
}

__global__ void k_count(const int* __restrict__ ei, const int* __restrict__ et, int E) {
    int e = blockIdx.x*blockDim.x + threadIdx.x;
    if (e >= E) return;
    atomicAdd(&dc_cnt[et[e]*NNODES + ei[E+e]], 1);
}

// shuffle-based hierarchical scan (same mapping: thread t owns chunk g = t*9+i)
__global__ void k_scan(int E) {
    __shared__ int ws[32];
    int tid = threadIdx.x;
    int lane = tid & 31, warp = tid >> 5;
    int c[9]; int s = 0;
    #pragma unroll
    for (int i = 0; i < 9; i++) {
        int g = tid*9 + i;
        c[i] = (g < NBUCKET) ? dc_cnt[g] : 0;
        s += c[i];
    }
    // inclusive warp scan of s
    int si = s;
    #pragma unroll
    for (int d = 1; d < 32; d <<= 1) {
        int v = __shfl_up_sync(0xffffffffu, si, d);
        if (lane >= d) si += v;
    }
    if (lane == 31) ws[warp] = si;
    __syncthreads();
    if (warp == 0) {
        int w = ws[lane];
        #pragma unroll
        for (int d = 1; d < 32; d <<= 1) {
            int v = __shfl_up_sync(0xffffffffu, w, d);
            if (lane >= d) w += v;
        }
        ws[lane] = w;   // inclusive over warps
    }
    __syncthreads();
    int run = si - s + (warp > 0 ? ws[warp-1] : 0);   // exclusive prefix of this thread's chunk
    #pragma unroll
    for (int i = 0; i < 9; i++) {
        int g = tid*9 + i;
        if (g < NBUCKET) {
            dc_off[g] = run;
            dc_cur[g] = run;
            dc_inv[g] = 1.0f / (float)(c[i] > 1 ? c[i] : 1);
            run += c[i];
        }
    }
    if (tid == 0) dc_off[NBUCKET] = E;
}

__global__ void k_fill(const int* __restrict__ ei, const int* __restrict__ et, int E) {
    int e = blockIdx.x*blockDim.x + threadIdx.x;
    if (e >= E) return;
    int g = et[e]*NNODES + ei[E+e];
    int p = atomicAdd(&dc_cur[g], 1);
    dc_src[p] = ei[e];
}

// ---------------- temporal feature extraction (proven, verbatim) ----------------
__global__ void __launch_bounds__(128) k_temporal(const float* __restrict__ obs,
    const float* __restrict__ ws1, const float* __restrict__ bs1,
    const float* __restrict__ ws2, const float* __restrict__ bs2,
    const float* __restrict__ wm1, const float* __restrict__ bm1,
    const float* __restrict__ wm2, const float* __restrict__ bm2)
{
    extern __shared__ float sm[];
    float* s_ob   = sm;                 // 150*129 = 19350
    float* s_ws2t = sm + 19350;         // 2880  [t][c][o]
    float* s_wm2t = sm + 19350 + 2880;  // 1800  [t][c][o]
    float* s_wm1  = s_wm2t + 1800;      // 189
    float* s_ws1  = s_wm1  + 189;       // 27
    float* s_bs1  = s_ws1  + 27;        // 3
    float* s_bm1  = s_bs1  + 3;         // 3
    float* s_bs2  = s_bm1  + 3;         // 20
    float* s_bm2  = s_bs2  + 20;        // 20
    int tid = threadIdx.x;

    for (int i = tid; i < 2880; i += 128) {
        int o = i/144, c = (i/48)%3, t = i%48;        // ws2 (20,3,1,48)
        s_ws2t[(t*3+c)*20 + o] = __ldg(&ws2[i]);
    }
    for (int i = tid; i < 1800; i += 128) {
        int o = i/90, c = (i/30)%3, t = i%30;         // wm2 (20,3,1,30)
        s_wm2t[(t*3+c)*20 + o] = __ldg(&wm2[i]);
    }
    for (int i = tid; i < 189; i += 128) s_wm1[i] = __ldg(&wm1[i]);
    if (tid < 27) s_ws1[tid] = __ldg(&ws1[tid]);
    if (tid < 3)  { s_bs1[tid] = __ldg(&bs1[tid]); s_bm1[tid] = __ldg(&bm1[tid]); }
    if (tid < 20) { s_bs2[tid] = __ldg(&bs2[tid]); s_bm2[tid] = __ldg(&bm2[tid]); }

    int idx0 = blockIdx.x*128;
    for (int i = tid; i < 128*150; i += 128) {
        int slot = i/150, rem = i%150, c = rem/50, t = rem%50;
        int g = idx0 + slot; int b = g/NNODES, n = g%NNODES;
        s_ob[(c*50+t)*OBSTR + slot] = __ldg(&obs[(((size_t)(b*3+c))*NNODES + n)*50 + t]);
    }
    __syncthreads();

    const float* myob = s_ob + tid;
    float* xo = d_x + (size_t)(idx0 + tid)*FEAT;

    // ---- long path ----
    for (int c = 0; c < 3; c++) {
        float m = myob[(c*50)*OBSTR];
        for (int t = 1; t < 50; t++) m = fmaxf(m, myob[(c*50+t)*OBSTR]);
        xo[40+c] = fmaxf(m, 0.f);
    }

    // ---- short path ----
    {
        float acc[20];
        #pragma unroll
        for (int o = 0; o < 20; o++) acc[o] = s_bs2[o];
        float x0[3], x1[3];
        #pragma unroll
        for (int c = 0; c < 3; c++) { x0[c] = myob[(c*50+0)*OBSTR]; x1[c] = myob[(c*50+1)*OBSTR]; }
        for (int t = 0; t < 48; t++) {
            float x2[3];
            #pragma unroll
            for (int c = 0; c < 3; c++) x2[c] = myob[(c*50+t+2)*OBSTR];
            float s1[3];
            #pragma unroll
            for (int co = 0; co < 3; co++) {
                float v = s_bs1[co];
                #pragma unroll
                for (int ci = 0; ci < 3; ci++)
                    v += x0[ci]*s_ws1[(co*3+ci)*3+0] + x1[ci]*s_ws1[(co*3+ci)*3+1] + x2[ci]*s_ws1[(co*3+ci)*3+2];
                s1[co] = fmaxf(v, 0.f);
            }
            const float* wt = s_ws2t + t*60;
            #pragma unroll
            for (int c = 0; c < 3; c++) {
                float v = s1[c];
                const float* w = wt + c*20;
                #pragma unroll
                for (int o = 0; o < 20; o++) acc[o] += v*w[o];
            }
            #pragma unroll
            for (int c = 0; c < 3; c++) { x0[c] = x1[c]; x1[c] = x2[c]; }
        }
        #pragma unroll
        for (int o = 0; o < 20; o++) xo[o] = fmaxf(acc[o], 0.f);
    }

    // ---- mid path ----
    {
        float accm[20];
        #pragma unroll
        for (int o = 0; o < 20; o++) accm[o] = s_bm2[o];
        for (int pass = 0; pass < 2; pass++) {
            float m1[3][15];
            #pragma unroll
            for (int co = 0; co < 3; co++)
                #pragma unroll
                for (int tt = 0; tt < 15; tt++) m1[co][tt] = s_bm1[co];
            for (int ci = 0; ci < 3; ci++) {
                for (int k = 0; k < 21; k++) {
                    float w0 = s_wm1[(0*3+ci)*21+k];
                    float w1 = s_wm1[(1*3+ci)*21+k];
                    float w2 = s_wm1[(2*3+ci)*21+k];
                    const float* pb = myob + (ci*50 + pass*15 + k)*OBSTR;
                    #pragma unroll
                    for (int tt = 0; tt < 15; tt++) {
                        float ov = pb[tt*OBSTR];
                        m1[0][tt] += ov*w0; m1[1][tt] += ov*w1; m1[2][tt] += ov*w2;
                    }
                }
            }
            #pragma unroll
            for (int tt = 0; tt < 15; tt++) {
                const float* wt = s_wm2t + (pass*15+tt)*60;
                #pragma unroll
                for (int c = 0; c < 3; c++) {
                    float v = fmaxf(m1[c][tt], 0.f);
                    const float* w = wt + c*20;
                    #pragma unroll
                    for (int o = 0; o < 20; o++) accm[o] += v*w[o];
                }
            }
        }
        #pragma unroll
        for (int o = 0; o < 20; o++) xo[20+o] = fmaxf(accm[o], 0.f);
    }
}

// ---------------- RGCN layer: warp-per-bucket gather + proven matmul ----------------
// agg_s layout: [r][nl][b][f]  (linear in idx = b*FEAT+f)
__global__ void __launch_bounds__(256) k_rgcn(int layer,
                       const float* __restrict__ root,
                       const float* __restrict__ rel,
                       const float* __restrict__ bias)
{
    extern __shared__ float sm[];
    float* w_s    = sm;              // 4*1849: [root, rel0, rel1, rel2], row-major [f][o]
    float* bias_s = sm + 7396;       // 43
    float* agg_s  = sm + 7439;       // [r][nl][b][f] = 3*8*16*43 = 16512

    const float* xin  = (layer == 0) ? d_x  : d_h1;
    float*       xout = (layer == 0) ? d_h1 : d_h2;

    int tid = threadIdx.x;
    for (int i = tid; i < 1849;   i += 256) w_s[i]       = __ldg(root + i);
    for (int i = tid; i < 3*1849; i += 256) w_s[1849+i]  = __ldg(rel + i);
    if (tid < FEAT) bias_s[tid] = bias[tid];

    // ---- gather: warp per (nl, r) bucket; lane owns slots idx = lane + 32k ----
    int lane = tid & 31;
    int warp = tid >> 5;   // 0..7
    int offk[22];
    #pragma unroll
    for (int k = 0; k < 22; k++) {
        int idx = lane + 32*k;
        int ii = (idx < BATCH*FEAT) ? idx : 0;
        int b = ii / FEAT, f = ii - b*FEAT;
        offk[k] = b*NNODES*FEAT + f;
    }
    bool v21 = lane < (BATCH*FEAT - 21*32);   // lane < 16

    int node0 = blockIdx.x * GBN;
    #pragma unroll
    for (int round = 0; round < 3; round++) {
        int q  = warp + 8*round;        // 0..23
        int nl = q / NREL, r = q - nl*NREL;
        int g  = r*NNODES + node0 + nl;
        int s_ = dc_off[g], e_ = dc_off[g+1];
        float a[22];
        #pragma unroll
        for (int k = 0; k < 22; k++) a[k] = 0.f;
        for (int e = s_; e < e_; e++) {
            int so = __ldg(&dc_src[e]) * FEAT;
            #pragma unroll
            for (int k = 0; k < 21; k++) a[k] += __ldg(xin + offk[k] + so);
            if (v21) a[21] += __ldg(xin + offk[21] + so);
        }
        float inv = dc_inv[g];
        float* ab = agg_s + (size_t)((r*GBN + nl)*BATCH)*FEAT;
        #pragma unroll
        for (int k = 0; k < 21; k++) ab[lane + 32*k] = a[k]*inv;
        if (v21) ab[lane + 32*21] = a[21]*inv;
    }
    __syncthreads();

    // ---- matmul: thread -> (half, nl, b); half splits the 43 outputs 22/21 ----
    int b    = tid & 15;
    int nl   = (tid >> 4) & 7;
    int half = tid >> 7;
    int n    = node0 + nl;
    int o0   = half * 22;

    float outv[22];
    #pragma unroll
    for (int oo = 0; oo < 22; oo++) outv[oo] = bias_s[o0 + oo];   // oo=21,half=1 reads junk, never stored

    const float* xr = xin + (size_t)(b*NNODES + n)*FEAT;
    for (int f = 0; f < FEAT; f++) {
        float xv = __ldg(xr + f);
        const float* wr = w_s + f*FEAT + o0;
        #pragma unroll
        for (int oo = 0; oo < 22; oo++) outv[oo] += xv * wr[oo];
    }
    #pragma unroll
    for (int r = 0; r < NREL; r++) {
        const float* ar = agg_s + (size_t)(((r*GBN + nl)*BATCH) + b)*FEAT;
        const float* wb = w_s + (1 + r)*1849 + o0;
        for (int f = 0; f < FEAT; f++) {
            float av = ar[f];
            const float* wr = wb + f*FEAT;
            #pragma unroll
            for (int oo = 0; oo < 22; oo++) outv[oo] += av * wr[oo];
        }
    }

    float* yo = xout + (size_t)(b*NNODES + n)*FEAT;
    #pragma unroll
    for (int oo = 0; oo < 22; oo++) {
        int o = o0 + oo;
        if (o < FEAT) {
            float v = outv[oo];
            yo[o] = v > 0.f ? v : 0.01f*v;     // leaky_relu 0.01
        }
    }
}

// ---------------- head (proven, verbatim) ----------------
__global__ void k_head(const float* __restrict__ la, const int* __restrict__ sel,
                       const float* __restrict__ wf, const float* __restrict__ bf,
                       float* __restrict__ out)
{
    __shared__ float sh[501];
    __shared__ float rbuf[16];
    int b = blockIdx.x, t = threadIdx.x;
    if (t == 0) sh[0] = 0.f;                 // cash logit
    if (t < 500) {
        int node = __ldg(&sel[t]);
        float v = __ldg(bf) + __ldg(wf)*__ldg(&la[b*501 + 1 + t]);
        const float* xr = d_x  + (size_t)(b*NNODES + node)*FEAT;
        const float* hr = d_h2 + (size_t)(b*NNODES + node)*FEAT;
        #pragma unroll
        for (int f = 0; f < FEAT; f++) v += __ldg(&wf[1 + f])  * __ldg(xr + f);
        #pragma unroll
        for (int f = 0; f < FEAT; f++) v += __ldg(&wf[44 + f]) * __ldg(hr + f);
        sh[1 + t] = v;
    }
    __syncthreads();

    float m = -1e30f;
    for (int i = t; i < 501; i += 512) m = fmaxf(m, sh[i]);
    #pragma unroll
    for (int off = 16; off; off >>= 1) m = fmaxf(m, __shfl_xor_sync(0xffffffffu, m, off));
    if ((t & 31) == 0) rbuf[t >> 5] = m;
    __syncthreads();
    if (t == 0) { float mm = rbuf[0]; for (int w = 1; w < 16; w++) mm = fmaxf(mm, rbuf[w]); rbuf[0] = mm; }
    __syncthreads();
    float gm = rbuf[0];
    __syncthreads();

    float ssum = 0.f;
    for (int i = t; i < 501; i += 512) { float e = __expf(sh[i] - gm); sh[i] = e; ssum += e; }
    #pragma unroll
    for (int off = 16; off; off >>= 1) ssum += __shfl_xor_sync(0xffffffffu, ssum, off);
    if ((t & 31) == 0) rbuf[t >> 5] = ssum;
    __syncthreads();
    if (t == 0) { float s2 = 0.f; for (int w = 0; w < 16; w++) s2 += rbuf[w]; rbuf[0] = s2; }
    __syncthreads();
    float invs = 1.0f / rbuf[0];
    for (int i = t; i < 501; i += 512) out[b*501 + i] = sh[i] * invs;
}

// ---------------- launch ----------------
extern "C" void kernel_launch(void* const* d_in, const int* in_sizes, int n_in,
                              void* d_out, int out_size)
{
    const float* obs   = (const float*)d_in[0];
    const float* la    = (const float*)d_in[1];
    const int*   ei    = (const int*)  d_in[2];
    const int*   et    = (const int*)  d_in[3];
    const int*   sel   = (const int*)  d_in[4];
    const float* ws1   = (const float*)d_in[5];
    const float* bs1   = (const float*)d_in[6];
    const float* ws2   = (const float*)d_in[7];
    const float* bs2   = (const float*)d_in[8];
    const float* wm1   = (const float*)d_in[9];
    const float* bm1   = (const float*)d_in[10];
    const float* wm2   = (const float*)d_in[11];
    const float* bm2   = (const float*)d_in[12];
    const float* root1 = (const float*)d_in[13];
    const float* rel1  = (const float*)d_in[14];
    const float* bias1 = (const float*)d_in[15];
    const float* root2 = (const float*)d_in[16];
    const float* rel2  = (const float*)d_in[17];
    const float* bias2 = (const float*)d_in[18];
    const float* wf    = (const float*)d_in[19];
    const float* bf    = (const float*)d_in[20];
    float* out = (float*)d_out;

    int E = in_sizes[3];   // 96000

    // temporal FIRST (independent of CSR) -> launch #5 is k_rgcn layer 1 for ncu -s 5
    int smem_t = (150*OBSTR + 2880 + 1800 + 189 + 27 + 3 + 3 + 20 + 20) * (int)sizeof(float);
    cudaFuncSetAttribute(k_temporal, cudaFuncAttributeMaxDynamicSharedMemorySize, smem_t);
    k_temporal<<<ROWS/128, 128, smem_t>>>(obs, ws1, bs1, ws2, bs2, wm1, bm1, wm2, bm2);

    // CSR build
    k_zero <<<(NBUCKET + 255)/256, 256>>>();
    k_count<<<(E + 255)/256,       256>>>(ei, et, E);
    k_scan <<<1, 1024>>>(E);
    k_fill <<<(E + 255)/256,       256>>>(ei, et, E);

    // RGCN layers (launches #5 and #6)
    int smem = (7396 + 43 + NREL*GBN*BATCH*FEAT) * (int)sizeof(float);   // ~93.6 KB
    cudaFuncSetAttribute(k_rgcn, cudaFuncAttributeMaxDynamicSharedMemorySize, smem);
    k_rgcn<<<NNODES/GBN, 256, smem>>>(0, root1, rel1, bias1);
    k_rgcn<<<NNODES/GBN, 256, smem>>>(1, root2, rel2, bias2);

    // head
    k_head<<<BATCH, 512>>>(la, sel, wf, bf, out);
}

// round 10
// speedup vs baseline: 1.3046x; 1.3046x over previous
#include <cuda_runtime.h>

#define NNODES 3000
#define BATCH  16
#define FEAT   43
#define NREL   3
#define NBUCKET (NREL*NNODES)
#define ROWS   (BATCH*NNODES)     // 48000
#define GBN    4                  // nodes per block in RGCN kernel (3 CTAs/SM)
#define OBSTR  129                // padded stride for obs staging (bank-conflict free)
#define FILLBLK 750               // fill-role blocks in fused kernel (96000/128)

// ---------------- scratch (static __device__, no allocation) ----------------
__device__ float d_x [BATCH*NNODES*FEAT];   // temporal features
__device__ float d_h1[BATCH*NNODES*FEAT];   // after RGCN layer 1
__device__ float d_h2[BATCH*NNODES*FEAT];   // after RGCN layer 2
__device__ int   dc_cnt[NBUCKET];
__device__ int   dc_off[NBUCKET+1];
__device__ int   dc_cur[NBUCKET];
__device__ float dc_inv[NBUCKET];
__device__ int   dc_src[96000];

// ---------------- CSR build ----------------
__global__ void k_count(const int* __restrict__ ei, const int* __restrict__ et, int E) {
    int e = blockIdx.x*blockDim.x + threadIdx.x;
    if (e >= E) return;
    atomicAdd(&dc_cnt[et[e]*NNODES + ei[E+e]], 1);
}

// shuffle scan; self-zeros dc_cnt for the next graph replay (BSS starts zero)
__global__ void k_scan(int E) {
    __shared__ int ws[32];
    int tid = threadIdx.x;
    int lane = tid & 31, warp = tid >> 5;
    int c[9]; int s = 0;
    #pragma unroll
    for (int i = 0; i < 9; i++) {
        int g = tid*9 + i;
        if (g < NBUCKET) { c[i] = dc_cnt[g]; dc_cnt[g] = 0; }
        else c[i] = 0;
        s += c[i];
    }
    int si = s;
    #pragma unroll
    for (int d = 1; d < 32; d <<= 1) {
        int v = __shfl_up_sync(0xffffffffu, si, d);
        if (lane >= d) si += v;
    }
    if (lane == 31) ws[warp] = si;
    __syncthreads();
    if (warp == 0) {
        int w = ws[lane];
        #pragma unroll
        for (int d = 1; d < 32; d <<= 1) {
            int v = __shfl_up_sync(0xffffffffu, w, d);
            if (lane >= d) w += v;
        }
        ws[lane] = w;
    }
    __syncthreads();
    int run = si - s + (warp > 0 ? ws[warp-1] : 0);
    #pragma unroll
    for (int i = 0; i < 9; i++) {
        int g = tid*9 + i;
        if (g < NBUCKET) {
            dc_off[g] = run;
            dc_cur[g] = run;
            dc_inv[g] = 1.0f / (float)(c[i] > 1 ? c[i] : 1);
            run += c[i];
        }
    }
    if (tid == 0) dc_off[NBUCKET] = E;
}

// ---------------- fused fill + temporal (independent roles, disjoint blocks) ----------------
__global__ void __launch_bounds__(128) k_fill_temporal(
    const int* __restrict__ ei, const int* __restrict__ et, int E,
    const float* __restrict__ obs,
    const float* __restrict__ ws1, const float* __restrict__ bs1,
    const float* __restrict__ ws2, const float* __restrict__ bs2,
    const float* __restrict__ wm1, const float* __restrict__ bm1,
    const float* __restrict__ wm2, const float* __restrict__ bm2)
{
    if (blockIdx.x < FILLBLK) {
        // ---- fill role ----
        int e = blockIdx.x*128 + threadIdx.x;
        if (e < E) {
            int g = et[e]*NNODES + ei[E+e];
            int p = atomicAdd(&dc_cur[g], 1);
            dc_src[p] = ei[e];
        }
        return;
    }
    // ---- temporal role (proven round-5 body) ----
    extern __shared__ float sm[];
    float* s_ob   = sm;                 // 150*129 = 19350
    float* s_ws2t = sm + 19350;         // 2880  [t][c][o]
    float* s_wm2t = sm + 19350 + 2880;  // 1800  [t][c][o]
    float* s_wm1  = s_wm2t + 1800;      // 189
    float* s_ws1  = s_wm1  + 189;       // 27
    float* s_bs1  = s_ws1  + 27;        // 3
    float* s_bm1  = s_bs1  + 3;         // 3
    float* s_bs2  = s_bm1  + 3;         // 20
    float* s_bm2  = s_bs2  + 20;        // 20
    int tid = threadIdx.x;

    for (int i = tid; i < 2880; i += 128) {
        int o = i/144, c = (i/48)%3, t = i%48;        // ws2 (20,3,1,48)
        s_ws2t[(t*3+c)*20 + o] = __ldg(&ws2[i]);
    }
    for (int i = tid; i < 1800; i += 128) {
        int o = i/90, c = (i/30)%3, t = i%30;         // wm2 (20,3,1,30)
        s_wm2t[(t*3+c)*20 + o] = __ldg(&wm2[i]);
    }
    for (int i = tid; i < 189; i += 128) s_wm1[i] = __ldg(&wm1[i]);
    if (tid < 27) s_ws1[tid] = __ldg(&ws1[tid]);
    if (tid < 3)  { s_bs1[tid] = __ldg(&bs1[tid]); s_bm1[tid] = __ldg(&bm1[tid]); }
    if (tid < 20) { s_bs2[tid] = __ldg(&bs2[tid]); s_bm2[tid] = __ldg(&bm2[tid]); }

    int idx0 = (blockIdx.x - FILLBLK)*128;
    for (int i = tid; i < 128*150; i += 128) {
        int slot = i/150, rem = i%150, c = rem/50, t = rem%50;
        int g = idx0 + slot; int b = g/NNODES, n = g%NNODES;
        s_ob[(c*50+t)*OBSTR + slot] = __ldg(&obs[(((size_t)(b*3+c))*NNODES + n)*50 + t]);
    }
    __syncthreads();

    const float* myob = s_ob + tid;
    float* xo = d_x + (size_t)(idx0 + tid)*FEAT;

    // ---- long path ----
    for (int c = 0; c < 3; c++) {
        float m = myob[(c*50)*OBSTR];
        for (int t = 1; t < 50; t++) m = fmaxf(m, myob[(c*50+t)*OBSTR]);
        xo[40+c] = fmaxf(m, 0.f);
    }

    // ---- short path ----
    {
        float acc[20];
        #pragma unroll
        for (int o = 0; o < 20; o++) acc[o] = s_bs2[o];
        float x0[3], x1[3];
        #pragma unroll
        for (int c = 0; c < 3; c++) { x0[c] = myob[(c*50+0)*OBSTR]; x1[c] = myob[(c*50+1)*OBSTR]; }
        for (int t = 0; t < 48; t++) {
            float x2[3];
            #pragma unroll
            for (int c = 0; c < 3; c++) x2[c] = myob[(c*50+t+2)*OBSTR];
            float s1[3];
            #pragma unroll
            for (int co = 0; co < 3; co++) {
                float v = s_bs1[co];
                #pragma unroll
                for (int ci = 0; ci < 3; ci++)
                    v += x0[ci]*s_ws1[(co*3+ci)*3+0] + x1[ci]*s_ws1[(co*3+ci)*3+1] + x2[ci]*s_ws1[(co*3+ci)*3+2];
                s1[co] = fmaxf(v, 0.f);
            }
            const float* wt = s_ws2t + t*60;
            #pragma unroll
            for (int c = 0; c < 3; c++) {
                float v = s1[c];
                const float* w = wt + c*20;
                #pragma unroll
                for (int o = 0; o < 20; o++) acc[o] += v*w[o];
            }
            #pragma unroll
            for (int c = 0; c < 3; c++) { x0[c] = x1[c]; x1[c] = x2[c]; }
        }
        #pragma unroll
        for (int o = 0; o < 20; o++) xo[o] = fmaxf(acc[o], 0.f);
    }

    // ---- mid path ----
    {
        float accm[20];
        #pragma unroll
        for (int o = 0; o < 20; o++) accm[o] = s_bm2[o];
        for (int pass = 0; pass < 2; pass++) {
            float m1[3][15];
            #pragma unroll
            for (int co = 0; co < 3; co++)
                #pragma unroll
                for (int tt = 0; tt < 15; tt++) m1[co][tt] = s_bm1[co];
            for (int ci = 0; ci < 3; ci++) {
                for (int k = 0; k < 21; k++) {
                    float w0 = s_wm1[(0*3+ci)*21+k];
                    float w1 = s_wm1[(1*3+ci)*21+k];
                    float w2 = s_wm1[(2*3+ci)*21+k];
                    const float* pb = myob + (ci*50 + pass*15 + k)*OBSTR;
                    #pragma unroll
                    for (int tt = 0; tt < 15; tt++) {
                        float ov = pb[tt*OBSTR];
                        m1[0][tt] += ov*w0; m1[1][tt] += ov*w1; m1[2][tt] += ov*w2;
                    }
                }
            }
            #pragma unroll
            for (int tt = 0; tt < 15; tt++) {
                const float* wt = s_wm2t + (pass*15+tt)*60;
                #pragma unroll
                for (int c = 0; c < 3; c++) {
                    float v = fmaxf(m1[c][tt], 0.f);
                    const float* w = wt + c*20;
                    #pragma unroll
                    for (int o = 0; o < 20; o++) accm[o] += v*w[o];
                }
            }
        }
        #pragma unroll
        for (int o = 0; o < 20; o++) xo[20+o] = fmaxf(accm[o], 0.f);
    }
}

// ---------------- RGCN layer: GBN=4, 3 CTAs/SM; balanced serial gather ----------------
// agg_s layout: [r][nl][b][f]
__global__ void __launch_bounds__(256) k_rgcn(int layer,
                       const float* __restrict__ root,
                       const float* __restrict__ rel,
                       const float* __restrict__ bias)
{
    extern __shared__ float sm[];
    float* w_s    = sm;              // 4*1849: [root, rel0, rel1, rel2], row-major [f][o]
    float* bias_s = sm + 7396;       // 43
    float* agg_s  = sm + 7439;       // [r][nl][b][f] = 3*4*16*43 = 8256

    const float* xin  = (layer == 0) ? d_x  : d_h1;
    float*       xout = (layer == 0) ? d_h1 : d_h2;

    int tid = threadIdx.x;
    for (int i = tid; i < 1849;   i += 256) w_s[i]       = __ldg(root + i);
    for (int i = tid; i < 3*1849; i += 256) w_s[1849+i]  = __ldg(rel + i);
    if (tid < FEAT) bias_s[tid] = bias[tid];

    // gather slots: thread owns (b,f) pairs idx = tid + j*256.
    // j=0,1 always valid (max 511 < 688); j=2 valid iff tid < 176.
    int bj[3], fj[3];
    const float* pj[3];
    #pragma unroll
    for (int j = 0; j < 3; j++) {
        int idx = tid + j*256;
        int ii = (idx < BATCH*FEAT) ? idx : 0;
        bj[j] = ii / FEAT; fj[j] = ii - bj[j]*FEAT;
        pj[j] = xin + (size_t)bj[j]*NNODES*FEAT + fj[j];
    }
    bool v2 = (tid + 2*256) < BATCH*FEAT;   // tid < 176

    int node0 = blockIdx.x * GBN;
    #pragma unroll
    for (int nl = 0; nl < GBN; nl++) {
        int n = node0 + nl;
        #pragma unroll
        for (int r = 0; r < NREL; r++) {
            int s_ = dc_off[r*NNODES + n], e_ = dc_off[r*NNODES + n + 1];
            float a0 = 0.f, a1 = 0.f, a2 = 0.f;
            for (int e = s_; e < e_; e++) {
                int o0 = __ldg(&dc_src[e]) * FEAT;
                a0 += __ldg(pj[0] + o0);
                a1 += __ldg(pj[1] + o0);
                if (v2) a2 += __ldg(pj[2] + o0);
            }
            float inv = dc_inv[r*NNODES + n];
            float* ab = agg_s + (size_t)((r*GBN + nl)*BATCH)*FEAT;
            ab[bj[0]*FEAT + fj[0]] = a0*inv;
            ab[bj[1]*FEAT + fj[1]] = a1*inv;
            if (v2) ab[bj[2]*FEAT + fj[2]] = a2*inv;
        }
    }
    __syncthreads();

    // matmul: thread -> (quarter, nl, b); quarter splits the 43 outputs 11/11/11/10(+1 junk)
    int b    = tid & 15;
    int nl   = (tid >> 4) & 3;
    int q    = tid >> 6;          // 0..3
    int n    = node0 + nl;
    int o0   = q * 11;

    float outv[11];
    #pragma unroll
    for (int oo = 0; oo < 11; oo++) outv[oo] = bias_s[o0 + oo];   // o=43 reads junk, never stored

    const float* xr = xin + (size_t)(b*NNODES + n)*FEAT;
    for (int f = 0; f < FEAT; f++) {
        float xv = __ldg(xr + f);
        const float* wr = w_s + f*FEAT + o0;
        #pragma unroll
        for (int oo = 0; oo < 11; oo++) outv[oo] += xv * wr[oo];
    }
    #pragma unroll
    for (int r = 0; r < NREL; r++) {
        const float* ar = agg_s + (size_t)(((r*GBN + nl)*BATCH) + b)*FEAT;
        const float* wb = w_s + (1 + r)*1849 + o0;
        for (int f = 0; f < FEAT; f++) {
            float av = ar[f];
            const float* wr = wb + f*FEAT;
            #pragma unroll
            for (int oo = 0; oo < 11; oo++) outv[oo] += av * wr[oo];
        }
    }

    float* yo = xout + (size_t)(b*NNODES + n)*FEAT;
    #pragma unroll
    for (int oo = 0; oo < 11; oo++) {
        int o = o0 + oo;
        if (o < FEAT) {
            float v = outv[oo];
            yo[o] = v > 0.f ? v : 0.01f*v;     // leaky_relu 0.01
        }
    }
}

// ---------------- head (proven, verbatim) ----------------
__global__ void k_head(const float* __restrict__ la, const int* __restrict__ sel,
                       const float* __restrict__ wf, const float* __restrict__ bf,
                       float* __restrict__ out)
{
    __shared__ float sh[501];
    __shared__ float rbuf[16];
    int b = blockIdx.x, t = threadIdx.x;
    if (t == 0) sh[0] = 0.f;                 // cash logit
    if (t < 500) {
        int node = __ldg(&sel[t]);
        float v = __ldg(bf) + __ldg(wf)*__ldg(&la[b*501 + 1 + t]);
        const float* xr = d_x  + (size_t)(b*NNODES + node)*FEAT;
        const float* hr = d_h2 + (size_t)(b*NNODES + node)*FEAT;
        #pragma unroll
        for (int f = 0; f < FEAT; f++) v += __ldg(&wf[1 + f])  * __ldg(xr + f);
        #pragma unroll
        for (int f = 0; f < FEAT; f++) v += __ldg(&wf[44 + f]) * __ldg(hr + f);
        sh[1 + t] = v;
    }
    __syncthreads();

    float m = -1e30f;
    for (int i = t; i < 501; i += 512) m = fmaxf(m, sh[i]);
    #pragma unroll
    for (int off = 16; off; off >>= 1) m = fmaxf(m, __shfl_xor_sync(0xffffffffu, m, off));
    if ((t & 31) == 0) rbuf[t >> 5] = m;
    __syncthreads();
    if (t == 0) { float mm = rbuf[0]; for (int w = 1; w < 16; w++) mm = fmaxf(mm, rbuf[w]); rbuf[0] = mm; }
    __syncthreads();
    float gm = rbuf[0];
    __syncthreads();

    float ssum = 0.f;
    for (int i = t; i < 501; i += 512) { float e = __expf(sh[i] - gm); sh[i] = e; ssum += e; }
    #pragma unroll
    for (int off = 16; off; off >>= 1) ssum += __shfl_xor_sync(0xffffffffu, ssum, off);
    if ((t & 31) == 0) rbuf[t >> 5] = ssum;
    __syncthreads();
    if (t == 0) { float s2 = 0.f; for (int w = 0; w < 16; w++) s2 += rbuf[w]; rbuf[0] = s2; }
    __syncthreads();
    float invs = 1.0f / rbuf[0];
    for (int i = t; i < 501; i += 512) out[b*501 + i] = sh[i] * invs;
}

// ---------------- launch ----------------
extern "C" void kernel_launch(void* const* d_in, const int* in_sizes, int n_in,
                              void* d_out, int out_size)
{
    const float* obs   = (const float*)d_in[0];
    const float* la    = (const float*)d_in[1];
    const int*   ei    = (const int*)  d_in[2];
    const int*   et    = (const int*)  d_in[3];
    const int*   sel   = (const int*)  d_in[4];
    const float* ws1   = (const float*)d_in[5];
    const float* bs1   = (const float*)d_in[6];
    const float* ws2   = (const float*)d_in[7];
    const float* bs2   = (const float*)d_in[8];
    const float* wm1   = (const float*)d_in[9];
    const float* bm1   = (const float*)d_in[10];
    const float* wm2   = (const float*)d_in[11];
    const float* bm2   = (const float*)d_in[12];
    const float* root1 = (const float*)d_in[13];
    const float* rel1  = (const float*)d_in[14];
    const float* bias1 = (const float*)d_in[15];
    const float* root2 = (const float*)d_in[16];
    const float* rel2  = (const float*)d_in[17];
    const float* bias2 = (const float*)d_in[18];
    const float* wf    = (const float*)d_in[19];
    const float* bf    = (const float*)d_in[20];
    float* out = (float*)d_out;

    int E = in_sizes[3];   // 96000

    int smem_t = (150*OBSTR + 2880 + 1800 + 189 + 27 + 3 + 3 + 20 + 20) * (int)sizeof(float);
    int smem_r = (7396 + 43 + NREL*GBN*BATCH*FEAT) * (int)sizeof(float);   // ~61.3 KB
    cudaFuncSetAttribute(k_fill_temporal, cudaFuncAttributeMaxDynamicSharedMemorySize, smem_t);
    cudaFuncSetAttribute(k_rgcn,          cudaFuncAttributeMaxDynamicSharedMemorySize, smem_r);

    // #0 count  (dc_cnt zeroed by previous scan; BSS-zero on first call)
    k_count<<<(E + 255)/256, 256>>>(ei, et, E);
    // #1 scan (+ self-zero dc_cnt)
    k_scan<<<1, 1024>>>(E);
    // #2 fused fill + temporal
    k_fill_temporal<<<FILLBLK + ROWS/128, 128, smem_t>>>(ei, et, E,
        obs, ws1, bs1, ws2, bs2, wm1, bm1, wm2, bm2);
    // #3, #4 RGCN layers   (#3 is what ncu captures)
    k_rgcn<<<NNODES/GBN, 256, smem_r>>>(0, root1, rel1, bias1);
    k_rgcn<<<NNODES/GBN, 256, smem_r>>>(1, root2, rel2, bias2);
    // #5 head
    k_head<<<BATCH, 512>>>(la, sel, wf, bf, out);
}